// round 15
// baseline (speedup 1.0000x reference)
#include <cuda_runtime.h>
#include <cuda_fp16.h>
#include <mma.h>

#define BB 4
#define TT 4096
#define SS 4096
#define DD 64
#define NITER 8
#define CAP 1024           // max nnz per row/col (expected ~515, max ~620)
#define RPB 8              // build rows per block

__device__ __half        g_K[(size_t)BB*TT*SS];      // 128 MB dense (GEMM only)
__device__ unsigned int  g_csr[(size_t)BB*TT*CAP];   // (s<<16)|half bits
__device__ unsigned int  g_csc[(size_t)BB*SS*CAP];   // (t<<16)|half bits
__device__ int           g_rlen[BB*TT];
__device__ int           g_clen[BB*SS];
__device__ float         g_u[BB*TT];
__device__ float         g_v[BB*SS];

// ---------------------------------------------------------------------------
__global__ void init0() {
    int i = blockIdx.x*blockDim.x + threadIdx.x;
    if (i < BB*SS) { g_clen[i] = 0; g_v[i] = 1.0f; }
}

__global__ void zero_out(float* __restrict__ out) {
    int i = blockIdx.x*blockDim.x + threadIdx.x;   // BB*TT*DD/4 float4
    ((float4*)out)[i] = make_float4(0.f,0.f,0.f,0.f);
}

// ---------------------------------------------------------------------------
// build: 8 t-rows per block; slocs staged in smem, smask as bitmask.
// dense K (half2, __stcs) + CSR (dual-ballot append) + CSC (atomic scatter)
// ---------------------------------------------------------------------------
__global__ void __launch_bounds__(256)
build_k(const float2* __restrict__ slocs,
        const float2* __restrict__ tlocs,
        const int* __restrict__ smask,
        const int* __restrict__ tmask) {
    __shared__ float2   s_loc[SS];          // 32 KB
    __shared__ unsigned s_msk[SS/32];       // 512 B
    __shared__ int cnt;

    int b  = blockIdx.y;
    int t0 = blockIdx.x * RPB;
    int lane = threadIdx.x & 31;
    unsigned lmask = (1u << lane) - 1u;
    const float inv_eps = 1.0f / (0.01f + 1e-8f);

    // stage source data
    for (int i = threadIdx.x; i < SS; i += 256) {
        s_loc[i] = slocs[b*SS + i];
        unsigned bal = __ballot_sync(0xffffffffu, smask[b*SS + i] != 0);
        if (lane == 0) s_msk[i >> 5] = bal;
    }
    __syncthreads();

    for (int r = 0; r < RPB; r++) {
        int t = t0 + r;
        float2 tl = tlocs[b*TT + t];
        bool tm = tmask[b*TT + t] != 0;
        __half2* dense = (__half2*)(g_K + ((size_t)(b*TT + t))*SS);
        unsigned int* row = g_csr + ((size_t)(b*TT + t))*CAP;

        if (threadIdx.x == 0) cnt = 0;
        __syncthreads();

        for (int j = threadIdx.x; j < SS/2; j += 256) {   // uniform 8 iters
            int s = 2*j;
            float2 p0 = s_loc[s], p1 = s_loc[s+1];
            unsigned mw = s_msk[s >> 5];
            float dx0 = tl.x - p0.x, dy0 = tl.y - p0.y;
            float dx1 = tl.x - p1.x, dy1 = tl.y - p1.y;
            float d0 = dx0*dx0 + dy0*dy0;
            float d1 = dx1*dx1 + dy1*dy1;
            bool v0 = tm && ((mw >> (s    & 31)) & 1u) && (d0 < 0.04f);
            bool v1 = tm && ((mw >> ((s+1)& 31)) & 1u) && (d1 < 0.04f);
            float k0 = v0 ? __expf(-d0*inv_eps) : 0.0f;
            float k1 = v1 ? __expf(-d1*inv_eps) : 0.0f;
            __half h0 = __float2half_rn(k0), h1 = __float2half_rn(k1);
            __stcs(dense + j, __halves2half2(h0, h1));

            unsigned m0 = __ballot_sync(0xffffffffu, v0);
            unsigned m1 = __ballot_sync(0xffffffffu, v1);
            int tot = __popc(m0) + __popc(m1);
            int base = 0;
            if (lane == 0 && tot) base = atomicAdd(&cnt, tot);
            base = __shfl_sync(0xffffffffu, base, 0);
            if (v0) {
                int off = base + __popc(m0 & lmask);
                unsigned short kb = __half_as_ushort(h0);
                if (off < CAP) row[off] = ((unsigned)s << 16) | kb;
                int slot = atomicAdd(&g_clen[b*SS + s], 1);
                if (slot < CAP)
                    g_csc[((size_t)(b*SS + s))*CAP + slot] = ((unsigned)t << 16) | kb;
            }
            if (v1) {
                int off = base + __popc(m0) + __popc(m1 & lmask);
                unsigned short kb = __half_as_ushort(h1);
                if (off < CAP) row[off] = ((unsigned)(s+1) << 16) | kb;
                int slot = atomicAdd(&g_clen[b*SS + s + 1], 1);
                if (slot < CAP)
                    g_csc[((size_t)(b*SS + s + 1))*CAP + slot] = ((unsigned)t << 16) | kb;
            }
        }
        __syncthreads();
        if (threadIdx.x == 0) g_rlen[b*TT + t] = (cnt < CAP) ? cnt : CAP;
    }
}

// ---------------------------------------------------------------------------
// u[t] = 1 / sum_{row t} K*v[s]   one warp per row
// phase 1: batch-load ALL structure words (32-deep MLP); phase 2: gathers
// ---------------------------------------------------------------------------
__global__ void u_sparse() {
    int b = blockIdx.y;
    int r = blockIdx.x*8 + (threadIdx.x >> 5);
    int lane = threadIdx.x & 31;
    int n = g_rlen[b*TT + r];
    const uint4* row = (const uint4*)(g_csr + ((size_t)(b*TT + r))*CAP);
    const float* v = g_v + b*SS;
    int nit = (n + 127) >> 7;                 // <= 8
    uint4 q[8];
    #pragma unroll
    for (int j = 0; j < 8; j++)
        if (j < nit) q[j] = row[j*32 + lane];
    float a0=0.f, a1=0.f, a2=0.f, a3=0.f;
    #pragma unroll
    for (int j = 0; j < 8; j++) {
        if (j < nit) {
            int e = j*128 + lane*4;
            if (e   < n) a0 += __half2float(__ushort_as_half((unsigned short)q[j].x)) * v[q[j].x >> 16];
            if (e+1 < n) a1 += __half2float(__ushort_as_half((unsigned short)q[j].y)) * v[q[j].y >> 16];
            if (e+2 < n) a2 += __half2float(__ushort_as_half((unsigned short)q[j].z)) * v[q[j].z >> 16];
            if (e+3 < n) a3 += __half2float(__ushort_as_half((unsigned short)q[j].w)) * v[q[j].w >> 16];
        }
    }
    float acc = (a0 + a1) + (a2 + a3);
    for (int o = 16; o; o >>= 1) acc += __shfl_down_sync(0xffffffffu, acc, o);
    if (lane == 0)
        g_u[b*TT + r] = (acc > 0.0f) ? 1.0f/acc : 0.0f;   // u==0 <=> no source
}

__global__ void v_sparse() {
    int b = blockIdx.y;
    int c = blockIdx.x*8 + (threadIdx.x >> 5);
    int lane = threadIdx.x & 31;
    int n = g_clen[b*SS + c];
    if (n > CAP) n = CAP;
    const uint4* col = (const uint4*)(g_csc + ((size_t)(b*SS + c))*CAP);
    const float* u = g_u + b*TT;
    int nit = (n + 127) >> 7;
    uint4 q[8];
    #pragma unroll
    for (int j = 0; j < 8; j++)
        if (j < nit) q[j] = col[j*32 + lane];
    float a0=0.f, a1=0.f, a2=0.f, a3=0.f;
    #pragma unroll
    for (int j = 0; j < 8; j++) {
        if (j < nit) {
            int e = j*128 + lane*4;
            if (e   < n) a0 += __half2float(__ushort_as_half((unsigned short)q[j].x)) * u[q[j].x >> 16];
            if (e+1 < n) a1 += __half2float(__ushort_as_half((unsigned short)q[j].y)) * u[q[j].y >> 16];
            if (e+2 < n) a2 += __half2float(__ushort_as_half((unsigned short)q[j].z)) * u[q[j].z >> 16];
            if (e+3 < n) a3 += __half2float(__ushort_as_half((unsigned short)q[j].w)) * u[q[j].w >> 16];
        }
    }
    float acc = (a0 + a1) + (a2 + a3);
    for (int o = 16; o; o >>= 1) acc += __shfl_down_sync(0xffffffffu, acc, o);
    if (lane == 0)
        g_v[b*SS + c] = (acc > 0.0f) ? 1.0f/acc : 0.0f;
}

// ---------------------------------------------------------------------------
// out += gate(t)*u[t] * K[t, s-slice] * (v*feats)[s-slice]   per s-chunk CTA
// ---------------------------------------------------------------------------
#define GBT 128
#define GBS 32
#define SCH 8
#define SLEN (SS/SCH)      // 512
using namespace nvcuda;

__global__ void __launch_bounds__(256, 2)
gemm_out(const float* __restrict__ feats,
         const int* __restrict__ tmask,
         float* __restrict__ out) {
    __shared__ __align__(16) __half sK[GBT][GBS + 8];
    __shared__ __align__(16) __half sW[GBS][DD + 8];
    __shared__ __align__(16) float  sO[GBT][DD];

    int b  = blockIdx.y;
    int t0 = blockIdx.x * GBT;
    int sbase = blockIdx.z * SLEN;
    int warp = threadIdx.x >> 5;
    int wt = warp >> 1;
    int wd = warp & 1;

    wmma::fragment<wmma::accumulator,16,16,16,float> c[2][2];
    #pragma unroll
    for (int i = 0; i < 2; i++)
        #pragma unroll
        for (int j = 0; j < 2; j++)
            wmma::fill_fragment(c[i][j], 0.0f);

    for (int sc = 0; sc < SLEN/GBS; sc++) {
        int s0 = sbase + sc * GBS;
        for (int idx = threadIdx.x; idx < GBT*GBS/2; idx += 256) {
            int t = idx >> 4, c2 = idx & 15;
            unsigned int kk = __ldcs((const unsigned int*)
                (g_K + ((size_t)(b*TT + t0 + t))*SS + s0 + 2*c2));
            *(unsigned int*)(&sK[t][2*c2]) = kk;
        }
        for (int idx = threadIdx.x; idx < GBS*DD/4; idx += 256) {
            int s = idx >> 4, c4 = idx & 15;
            float4 f = *(const float4*)(feats + ((size_t)(b*SS + s0 + s))*DD + 4*c4);
            float vv = g_v[b*SS + s0 + s];
            *(__half2*)(&sW[s][4*c4    ]) = __floats2half2_rn(f.x*vv, f.y*vv);
            *(__half2*)(&sW[s][4*c4 + 2]) = __floats2half2_rn(f.z*vv, f.w*vv);
        }
        __syncthreads();
        #pragma unroll
        for (int kk = 0; kk < GBS; kk += 16) {
            wmma::fragment<wmma::matrix_a,16,16,16,__half,wmma::row_major> a[2];
            wmma::fragment<wmma::matrix_b,16,16,16,__half,wmma::row_major> bf[2];
            wmma::load_matrix_sync(a[0],  &sK[wt*32     ][kk], GBS + 8);
            wmma::load_matrix_sync(a[1],  &sK[wt*32 + 16][kk], GBS + 8);
            wmma::load_matrix_sync(bf[0], &sW[kk][wd*32     ], DD + 8);
            wmma::load_matrix_sync(bf[1], &sW[kk][wd*32 + 16], DD + 8);
            #pragma unroll
            for (int i = 0; i < 2; i++)
                #pragma unroll
                for (int j = 0; j < 2; j++)
                    wmma::mma_sync(c[i][j], a[i], bf[j], c[i][j]);
        }
        __syncthreads();
    }
    #pragma unroll
    for (int i = 0; i < 2; i++)
        #pragma unroll
        for (int j = 0; j < 2; j++)
            wmma::store_matrix_sync(&sO[wt*32 + i*16][wd*32 + j*16], c[i][j],
                                    DD, wmma::mem_row_major);
    __syncthreads();
    for (int idx = threadIdx.x; idx < GBT*DD/4; idx += 256) {
        int t = idx >> 4, c4 = idx & 15;
        int gt = b*TT + t0 + t;
        float scl = (tmask[gt] != 0) ? g_u[gt] : 0.0f;  // g_u==0 encodes !has_source
        float4 f = *(float4*)(&sO[t][4*c4]);
        float* o = out + ((size_t)gt)*DD + 4*c4;
        atomicAdd(o    , f.x*scl);
        atomicAdd(o + 1, f.y*scl);
        atomicAdd(o + 2, f.z*scl);
        atomicAdd(o + 3, f.w*scl);
    }
}

// ---------------------------------------------------------------------------
extern "C" void kernel_launch(void* const* d_in, const int* in_sizes, int n_in,
                              void* d_out, int out_size) {
    const float* feats  = (const float*)d_in[0];
    const float2* slocs = (const float2*)d_in[1];
    const float2* tlocs = (const float2*)d_in[2];
    const int* smask    = (const int*)d_in[3];   // bool -> int32 in harness
    const int* tmask    = (const int*)d_in[4];
    float* out = (float*)d_out;

    init0<<<(BB*SS + 255)/256, 256>>>();
    zero_out<<<(BB*TT*DD/4 + 255)/256, 256>>>(out);
    build_k<<<dim3(TT/RPB, BB), 256>>>(slocs, tlocs, smask, tmask);
    for (int it = 0; it < NITER; it++) {
        u_sparse<<<dim3(TT/8, BB), 256>>>();
        v_sparse<<<dim3(SS/8, BB), 256>>>();
    }
    gemm_out<<<dim3(TT/GBT, BB, SCH), 256>>>(feats, tmask, out);
}